// round 8
// baseline (speedup 1.0000x reference)
#include <cuda_runtime.h>

#define TT    512
#define BSZ   256
#define DIN   64
#define HH    128
#define G4    512            // gate rows per layer
#define K0    192
#define K1    256
#define NB0   48             // total k-blocks layer0
#define NB1   64             // total k-blocks layer1
#define NB0A  24             // L0a owns kb [0,24), L0b [24,48)
#define NB1A  32             // L1a owns kb [0,32), L1b [32,64)
#define BPC   8
#define NGRP  32
#define NTHR  512
#define PRING 8
#define NCTA  (NGRP*4)       // 128

// Blocked transposed weights: [kb][row] float4 = W[row][4kb..4kb+3]
__device__ float4 g_W0B[NB0 * G4];
__device__ float4 g_W1B[NB1 * G4];
// Cross-CTA traffic
__device__ float g_h0[TT][NGRP][BPC][HH];          // 64 MB, full length
__device__ float g_h1[TT][NGRP][BPC][HH];          // 64 MB, full length
__device__ float g_P0[PRING][NGRP][BPC][G4];       // L0a partial pre-acts
__device__ float g_P1[PRING][NGRP][BPC][G4];       // L1b partial pre-acts
__device__ int   g_fh0[TT][NGRP];
__device__ int   g_fh1[TT][NGRP];
__device__ int   g_fp0[TT][NGRP];
__device__ int   g_fp1[TT][NGRP];

__global__ void prep_kernel(const float* __restrict__ Wih0,
                            const float* __restrict__ Whh0,
                            const float* __restrict__ Wih1,
                            const float* __restrict__ Whh1)
{
    int idx = blockIdx.x * blockDim.x + threadIdx.x;
    int stride = gridDim.x * blockDim.x;
    for (int e = idx; e < TT * NGRP; e += stride) {
        ((int*)g_fh0)[e] = 0;
        ((int*)g_fh1)[e] = 0;
        ((int*)g_fp0)[e] = 0;
        ((int*)g_fp1)[e] = 0;
    }
    float* p0 = (float*)g_W0B;
    float* p1 = (float*)g_W1B;
    for (int e = idx; e < K0 * G4; e += stride) {
        int k = e / G4, g = e % G4;
        float v = (k < DIN) ? Wih0[g * DIN + k] : Whh0[g * HH + (k - DIN)];
        p0[((k >> 2) * G4 + g) * 4 + (k & 3)] = v;
    }
    for (int e = idx; e < K1 * G4; e += stride) {
        int k = e / G4, g = e % G4;
        float v = (k < HH) ? Wih1[g * HH + k] : Whh1[g * HH + (k - HH)];
        p1[((k >> 2) * G4 + g) * 4 + (k & 3)] = v;
    }
}

__device__ __forceinline__ void fma2(unsigned long long& d,
                                     unsigned long long a,
                                     unsigned long long b)
{
    asm("fma.rn.f32x2 %0, %1, %2, %0;" : "+l"(d) : "l"(a), "l"(b));
}
__device__ __forceinline__ float flo(unsigned long long v) {
    return __uint_as_float((unsigned)(v & 0xffffffffu));
}
__device__ __forceinline__ float fhi(unsigned long long v) {
    return __uint_as_float((unsigned)(v >> 32));
}
__device__ __forceinline__ float sigf(float x) {
    return __fdividef(1.0f, 1.0f + __expf(-x));
}
__device__ __forceinline__ float tanhfast(float x) {
    return 1.0f - __fdividef(2.0f, __expf(2.0f * x) + 1.0f);
}
__device__ __forceinline__ int ld_acq(const int* p) {
    int v;
    asm volatile("ld.acquire.gpu.global.s32 %0, [%1];" : "=r"(v) : "l"(p) : "memory");
    return v;
}
__device__ __forceinline__ void st_rel(int* p, int v) {
    asm volatile("st.release.gpu.global.s32 [%0], %1;" :: "l"(p), "r"(v) : "memory");
}
__device__ __forceinline__ float4 ldcg4(const float4* p) {
    float4 v;
    asm volatile("ld.global.cg.v4.f32 {%0,%1,%2,%3}, [%4];"
                 : "=f"(v.x), "=f"(v.y), "=f"(v.z), "=f"(v.w) : "l"(p) : "memory");
    return v;
}
__device__ __forceinline__ float ldcg(const float* p) {
    float v;
    asm volatile("ld.global.cg.f32 %0, [%1];" : "=f"(v) : "l"(p) : "memory");
    return v;
}
__device__ __forceinline__ void stcg(float* p, float v) {
    asm volatile("st.global.cg.f32 [%0], %1;" :: "l"(p), "f"(v) : "memory");
}

// dot over NB k-blocks for 8 batches; xbase rows separated by STRIDEF floats
template<int NB, int STRIDEF>
__device__ __forceinline__ void dot8(const ulonglong2* wp, const float* xbase,
                                     float* pre)
{
    unsigned long long acc[BPC];
    #pragma unroll
    for (int b = 0; b < BPC; ++b) acc[b] = 0ull;
    #pragma unroll 4
    for (int kb = 0; kb < NB; ++kb) {
        ulonglong2 w = wp[(size_t)kb * G4];
        #pragma unroll
        for (int b = 0; b < BPC; ++b) {
            ulonglong2 xv = *((const ulonglong2*)(xbase + b * STRIDEF) + kb);
            fma2(acc[b], w.x, xv.x);
            fma2(acc[b], w.y, xv.y);
        }
    }
    #pragma unroll
    for (int b = 0; b < BPC; ++b) pre[b] = flo(acc[b]) + fhi(acc[b]);
}

__global__ void __launch_bounds__(NTHR, 1)
lstm_kernel(const float* __restrict__ state,
            const float* __restrict__ b_ih0, const float* __restrict__ b_hh0,
            const float* __restrict__ b_ih1, const float* __restrict__ b_hh1,
            const float* __restrict__ W_out, const float* __restrict__ b_out,
            float* __restrict__ out)
{
    __shared__ __align__(16) float sx2[2][BPC][96];   // L0a: [x_t | h0[0..32)]
    __shared__ __align__(16) float sxs[BPC][HH];      // L0b/L1a/L1b x vector
    __shared__ float sg[BPC][G4];                     // combined pre-acts
    __shared__ float sh1[BPC][HH];                    // L1a: h1 for head
    __shared__ float swout[HH];
    __shared__ float sbout;

    const int grp  = blockIdx.x >> 2;
    const int role = blockIdx.x & 3;     // 0=L0a 1=L0b 2=L1a 3=L1b
    const int gb   = grp * BPC;
    const int tid  = threadIdx.x;
    const int r    = tid;                // gate row 0..511
    const int j    = tid & (HH - 1);     // act-phase unit
    const int bp   = tid >> 7;           // act-phase batch pair 0..3

    if (role == 0) {
        // ============ L0a: layer0 kb[0,24), x = [x_t | h0[0..32)] ============
        if (tid < 64) {   // zero h0 part of parity 0
            int b = tid >> 3, q = tid & 7;
            ((float4*)sx2[0][b])[16 + q] = make_float4(0.f, 0.f, 0.f, 0.f);
        }
        if (tid < 128) {  // x(0)
            int b = tid >> 4, q = tid & 15;
            ((float4*)sx2[0][b])[q] = ldcg4((const float4*)(state + (gb + b) * DIN) + q);
        }
        const ulonglong2* wp = (const ulonglong2*)g_W0B + r;
        __syncthreads();
        for (int t = 0; t < TT; ++t) {
            const int p = t & 1;
            if (t > 0) {
                if (tid == 0) while (ld_acq(&g_fh0[t - 1][grp]) == 0) { }
                __syncthreads();
                if (tid < 64) {   // h0[0..32)(t-1)
                    int b = tid >> 3, q = tid & 7;
                    ((float4*)sx2[p][b])[16 + q] =
                        ldcg4((const float4*)g_h0[t - 1][grp][b] + q);
                }
            }
            if (t + 1 < TT && tid < 128) {  // prefetch x(t+1)
                int b = tid >> 4, q = tid & 15;
                ((float4*)sx2[p ^ 1][b])[q] =
                    ldcg4((const float4*)(state + ((t + 1) * BSZ + gb + b) * DIN) + q);
            }
            __syncthreads();
            float pre[BPC];
            dot8<NB0A, 96>(wp, sx2[p][0], pre);
            #pragma unroll
            for (int b = 0; b < BPC; ++b)
                stcg(&g_P0[t & (PRING - 1)][grp][b][r], pre[b]);
            __threadfence();
            __syncthreads();
            if (tid == 0) st_rel(&g_fp0[t][grp], 1);
        }
    } else if (role == 1) {
        // ============ L0b: layer0 kb[24,48), x = h0[32..128); ACTOR ============
        const float bias = b_ih0[r] + b_hh0[r];
        for (int i = tid; i < BPC * 32; i += NTHR)  // zero x (h0(-1)=0)
            ((float4*)sxs[0])[i] = make_float4(0.f, 0.f, 0.f, 0.f);
        float c[2] = {0.0f, 0.0f};
        const ulonglong2* wp = (const ulonglong2*)g_W0B + (size_t)NB0A * G4 + r;
        __syncthreads();
        for (int t = 0; t < TT; ++t) {
            float pre[BPC];
            dot8<NB0 - NB0A, HH>(wp, sxs[0], pre);
            if (tid == 0) while (ld_acq(&g_fp0[t][grp]) == 0) { }
            __syncthreads();
            #pragma unroll
            for (int b = 0; b < BPC; ++b) {
                float pa = ldcg(&g_P0[t & (PRING - 1)][grp][b][r]);
                sg[b][r] = pre[b] + pa + bias;
            }
            __syncthreads();
            #pragma unroll
            for (int i = 0; i < 2; ++i) {
                int b = bp * 2 + i;
                float gi = sigf    (sg[b][j]);
                float gf = sigf    (sg[b][HH + j]);
                float gg = tanhfast(sg[b][2 * HH + j]);
                float go = sigf    (sg[b][3 * HH + j]);
                c[i] = gf * c[i] + gi * gg;
                float h = go * tanhfast(c[i]);
                if (j >= 32) sxs[b][j - 32] = h;          // own x for t+1
                stcg(&g_h0[t][grp][b][j], h);             // publish full h0
            }
            __threadfence();
            __syncthreads();
            if (tid == 0) st_rel(&g_fh0[t][grp], 1);
        }
    } else if (role == 2) {
        // ============ L1a: layer1 kb[0,32), x = h0(t); ACTOR + head ============
        const float bias = b_ih1[r] + b_hh1[r];
        if (tid < HH) swout[tid] = W_out[tid];
        if (tid == 0) sbout = b_out[0];
        float c[2] = {0.0f, 0.0f};
        const ulonglong2* wp = (const ulonglong2*)g_W1B + r;
        __syncthreads();
        for (int t = 0; t < TT; ++t) {
            if (tid == 0) while (ld_acq(&g_fh0[t][grp]) == 0) { }
            __syncthreads();
            if (tid < 256) {   // copy h0(t) -> smem
                int b = tid >> 5, q = tid & 31;
                ((float4*)sxs[b])[q] = ldcg4((const float4*)g_h0[t][grp][b] + q);
            }
            __syncthreads();
            float pre[BPC];
            dot8<NB1A, HH>(wp, sxs[0], pre);
            if (tid == 0) while (ld_acq(&g_fp1[t][grp]) == 0) { }
            __syncthreads();
            #pragma unroll
            for (int b = 0; b < BPC; ++b) {
                float pb = ldcg(&g_P1[t & (PRING - 1)][grp][b][r]);
                sg[b][r] = pre[b] + pb + bias;
            }
            __syncthreads();
            #pragma unroll
            for (int i = 0; i < 2; ++i) {
                int b = bp * 2 + i;
                float gi = sigf    (sg[b][j]);
                float gf = sigf    (sg[b][HH + j]);
                float gg = tanhfast(sg[b][2 * HH + j]);
                float go = sigf    (sg[b][3 * HH + j]);
                c[i] = gf * c[i] + gi * gg;
                float h = go * tanhfast(c[i]);
                sh1[b][j] = h;
                stcg(&g_h1[t][grp][b][j], h);             // to L1b
            }
            __threadfence();
            __syncthreads();
            if (tid == 0) st_rel(&g_fh1[t][grp], 1);
            if (tid < 64) {    // head: out[t] for 8 batches
                int b = tid >> 3, ch = tid & 7;
                float p = 0.0f;
                #pragma unroll
                for (int m = 0; m < 16; ++m) {
                    int u = ch * 16 + m;
                    p += sh1[b][u] * swout[u];
                }
                p += __shfl_down_sync(0xffffffffu, p, 4, 8);
                p += __shfl_down_sync(0xffffffffu, p, 2, 8);
                p += __shfl_down_sync(0xffffffffu, p, 1, 8);
                if (ch == 0) out[(size_t)t * BSZ + gb + b] = p + sbout;
            }
        }
    } else {
        // ============ L1b: layer1 kb[32,64), x = h1(t-1); producer ============
        for (int i = tid; i < BPC * 32; i += NTHR)   // h1(-1) = 0
            ((float4*)sxs[0])[i] = make_float4(0.f, 0.f, 0.f, 0.f);
        const ulonglong2* wp = (const ulonglong2*)g_W1B + (size_t)NB1A * G4 + r;
        __syncthreads();
        for (int t = 0; t < TT; ++t) {
            if (t > 0) {
                if (tid == 0) while (ld_acq(&g_fh1[t - 1][grp]) == 0) { }
                __syncthreads();
                if (tid < 256) {   // copy h1(t-1) -> smem
                    int b = tid >> 5, q = tid & 31;
                    ((float4*)sxs[b])[q] = ldcg4((const float4*)g_h1[t - 1][grp][b] + q);
                }
                __syncthreads();
            }
            float pre[BPC];
            dot8<NB1 - NB1A, HH>(wp, sxs[0], pre);
            #pragma unroll
            for (int b = 0; b < BPC; ++b)
                stcg(&g_P1[t & (PRING - 1)][grp][b][r], pre[b]);
            __threadfence();
            __syncthreads();
            if (tid == 0) st_rel(&g_fp1[t][grp], 1);
        }
    }
}

extern "C" void kernel_launch(void* const* d_in, const int* in_sizes, int n_in,
                              void* d_out, int out_size)
{
    const float* state = (const float*)d_in[0];
    const float* W_ih0 = (const float*)d_in[1];
    const float* W_hh0 = (const float*)d_in[2];
    const float* b_ih0 = (const float*)d_in[3];
    const float* b_hh0 = (const float*)d_in[4];
    const float* W_ih1 = (const float*)d_in[5];
    const float* W_hh1 = (const float*)d_in[6];
    const float* b_ih1 = (const float*)d_in[7];
    const float* b_hh1 = (const float*)d_in[8];
    const float* W_out = (const float*)d_in[9];
    const float* b_out = (const float*)d_in[10];
    float* out = (float*)d_out;

    prep_kernel<<<224, 512>>>(W_ih0, W_hh0, W_ih1, W_hh1);
    lstm_kernel<<<NCTA, NTHR>>>(state, b_ih0, b_hh0, b_ih1, b_hh1,
                                W_out, b_out, out);
}

// round 9
// speedup vs baseline: 1.8830x; 1.8830x over previous
#include <cuda_runtime.h>

#define TT    512
#define BSZ   256
#define DIN   64
#define HH    128
#define BPC   8
#define NGRP  32
#define NTHR  512
#define RPC   256        // rows per CTA: 4 gates x 64 units
#define UPC   64         // units per CTA
#define NB0   48         // k-blocks layer0 (K=192)
#define NB1   64         // k-blocks layer1 (K=256)
#define NB0H  24         // per k-segment
#define NB1H  32
#define NCTA  (NGRP*4)   // 128

// Blocked weights per (half, kb, row): float4 = W[grow][4kb..4kb+3]
__device__ float4 g_W0B[2 * NB0 * RPC];
__device__ float4 g_W1B[2 * NB1 * RPC];
// Whole-h handoff buffers (full sequence, no wrap) + flags
__device__ float g_h0[TT][NGRP][2][BPC][UPC];
__device__ float g_h1[TT][NGRP][2][BPC][UPC];
__device__ int   g_f0[TT][NGRP][2];
__device__ int   g_f1[TT][NGRP][2];

__global__ void prep_kernel(const float* __restrict__ Wih0,
                            const float* __restrict__ Whh0,
                            const float* __restrict__ Wih1,
                            const float* __restrict__ Whh1)
{
    int idx = blockIdx.x * blockDim.x + threadIdx.x;
    int stride = gridDim.x * blockDim.x;
    for (int e = idx; e < TT * NGRP * 2; e += stride) {
        ((int*)g_f0)[e] = 0;
        ((int*)g_f1)[e] = 0;
    }
    for (int e = idx; e < 2 * NB0 * RPC * 4; e += stride) {
        int i = e & 3, e2 = e >> 2;
        int r = e2 % RPC, e3 = e2 / RPC;
        int kb = e3 % NB0, half = e3 / NB0;
        int k = kb * 4 + i;
        int gate = r >> 6, ul = r & 63;
        int grow = gate * HH + half * UPC + ul;
        float v = (k < DIN) ? Wih0[grow * DIN + k] : Whh0[grow * HH + (k - DIN)];
        ((float*)g_W0B)[e] = v;
    }
    for (int e = idx; e < 2 * NB1 * RPC * 4; e += stride) {
        int i = e & 3, e2 = e >> 2;
        int r = e2 % RPC, e3 = e2 / RPC;
        int kb = e3 % NB1, half = e3 / NB1;
        int k = kb * 4 + i;
        int gate = r >> 6, ul = r & 63;
        int grow = gate * HH + half * UPC + ul;
        float v = (k < HH) ? Wih1[grow * HH + k] : Whh1[grow * HH + (k - HH)];
        ((float*)g_W1B)[e] = v;
    }
}

__device__ __forceinline__ void fma2(unsigned long long& d,
                                     unsigned long long a,
                                     unsigned long long b)
{
    asm("fma.rn.f32x2 %0, %1, %2, %0;" : "+l"(d) : "l"(a), "l"(b));
}
__device__ __forceinline__ float flo(unsigned long long v) {
    return __uint_as_float((unsigned)(v & 0xffffffffu));
}
__device__ __forceinline__ float fhi(unsigned long long v) {
    return __uint_as_float((unsigned)(v >> 32));
}
__device__ __forceinline__ float sigf(float x) {
    return __fdividef(1.0f, 1.0f + __expf(-x));
}
__device__ __forceinline__ float tanhfast(float x) {
    return 1.0f - __fdividef(2.0f, __expf(2.0f * x) + 1.0f);
}
__device__ __forceinline__ int ld_acq(const int* p) {
    int v;
    asm volatile("ld.acquire.gpu.global.s32 %0, [%1];" : "=r"(v) : "l"(p) : "memory");
    return v;
}
__device__ __forceinline__ void st_rel(int* p, int v) {
    asm volatile("st.release.gpu.global.s32 [%0], %1;" :: "l"(p), "r"(v) : "memory");
}
__device__ __forceinline__ float4 ldcg4(const float4* p) {
    float4 v;
    asm volatile("ld.global.cg.v4.f32 {%0,%1,%2,%3}, [%4];"
                 : "=f"(v.x), "=f"(v.y), "=f"(v.z), "=f"(v.w) : "l"(p) : "memory");
    return v;
}
__device__ __forceinline__ float ldcg(const float* p) {
    float v;
    asm volatile("ld.global.cg.f32 %0, [%1];" : "=f"(v) : "l"(p) : "memory");
    return v;
}
__device__ __forceinline__ void stcg(float* p, float v) {
    asm volatile("st.global.cg.f32 [%0], %1;" :: "l"(p), "f"(v) : "memory");
}

// dot over NBH k-blocks, 8 batches; xbase = batch0 row, XSF floats/row
template<int NBH, int XSF>
__device__ __forceinline__ void dotseg(const ulonglong2* __restrict__ wp,
                                       const float* __restrict__ xbase,
                                       int xoff, float* pre)
{
    unsigned long long acc[BPC];
    #pragma unroll
    for (int b = 0; b < BPC; ++b) acc[b] = 0ull;
    #pragma unroll 4
    for (int kb = 0; kb < NBH; ++kb) {
        ulonglong2 w = wp[(size_t)kb * RPC];
        #pragma unroll
        for (int b = 0; b < BPC; ++b) {
            ulonglong2 xv = ((const ulonglong2*)(xbase + (size_t)b * XSF))[xoff + kb];
            fma2(acc[b], w.x, xv.x);
            fma2(acc[b], w.y, xv.y);
        }
    }
    #pragma unroll
    for (int b = 0; b < BPC; ++b) pre[b] = flo(acc[b]) + fhi(acc[b]);
}

__global__ void __launch_bounds__(NTHR, 1)
lstm_kernel(const float* __restrict__ state,
            const float* __restrict__ b_ih0, const float* __restrict__ b_hh0,
            const float* __restrict__ b_ih1, const float* __restrict__ b_hh1,
            const float* __restrict__ W_out, const float* __restrict__ b_out,
            float* __restrict__ out)
{
    // role<2 (L0): sx[q][b][0..191] = [x_t | h0_full]; role>=2 (L1): flat
    // sxb rows of 256 = [h0_full(t) | h1_full(t-1)]
    __shared__ __align__(16) float sx[2][BPC][192];
    __shared__ float sg[BPC][2][RPC];   // k-seg partial pre-activations
    __shared__ float swout[HH];
    __shared__ float sbout;

    const int grp  = blockIdx.x >> 2;
    const int role = blockIdx.x & 3;    // 0,1 = L0 halves; 2,3 = L1 halves
    const int gb   = grp * BPC;
    const int tid  = threadIdx.x;
    const int seg  = tid >> 8;          // k-segment 0/1 (dot phase)
    const int r    = tid & 255;         // CTA-local row (gate*64 + unit)
    const int ua   = tid & 63;          // act-phase local unit
    const int ba   = (tid >> 6) & 7;    // act-phase batch

    if (role < 2) {
        // ==================== L0 half-CTA ====================
        const int half = role, peer = half ^ 1;
        const int gr0 = half * UPC + ua;
        const float bi = b_ih0[gr0]          + b_hh0[gr0];
        const float bf = b_ih0[HH + gr0]     + b_hh0[HH + gr0];
        const float bg = b_ih0[2*HH + gr0]   + b_hh0[2*HH + gr0];
        const float bo = b_ih0[3*HH + gr0]   + b_hh0[3*HH + gr0];
        for (int i2 = tid; i2 < 2 * BPC * HH; i2 += NTHR) {
            int pq = i2 / (BPC * HH), rem = i2 % (BPC * HH);
            sx[pq][rem / HH][DIN + (rem % HH)] = 0.0f;   // h0(-1) = 0
        }
        sx[0][ba][ua] = ldcg(state + (gb + ba) * DIN + ua);   // x(0)
        float cst = 0.0f;
        const ulonglong2* wp = (const ulonglong2*)g_W0B
                             + ((size_t)(half * NB0 + seg * NB0H) * RPC + r);
        __syncthreads();

        for (int t = 0; t < TT; ++t) {
            const int q = t & 1;
            if (t > 0) {
                while (ld_acq(&g_f0[t - 1][grp][peer]) == 0) { }
                if (tid < 128) {   // copy peer h0-half(t-1)
                    int b = tid >> 4, q4 = tid & 15;
                    ((float4*)&sx[q][b][DIN + peer * UPC])[q4] =
                        ldcg4((const float4*)&g_h0[t - 1][grp][peer][b][0] + q4);
                }
            }
            if (t + 1 < TT)       // prefetch x(t+1)
                sx[q ^ 1][ba][ua] =
                    ldcg(state + ((size_t)(t + 1) * BSZ + gb + ba) * DIN + ua);
            __syncthreads();

            float pre[BPC];
            dotseg<NB0H, 192>(wp, &sx[q][0][0], seg * NB0H, pre);
            #pragma unroll
            for (int b = 0; b < BPC; ++b) sg[b][seg][r] = pre[b];
            __syncthreads();

            {   // act: thread = (unit ua, batch ba), c in register
                float p0 = sg[ba][0][ua]           + sg[ba][1][ua]           + bi;
                float p1 = sg[ba][0][UPC + ua]     + sg[ba][1][UPC + ua]     + bf;
                float p2 = sg[ba][0][2*UPC + ua]   + sg[ba][1][2*UPC + ua]   + bg;
                float p3 = sg[ba][0][3*UPC + ua]   + sg[ba][1][3*UPC + ua]   + bo;
                float gi = sigf(p0), gf = sigf(p1);
                float gG = tanhfast(p2), go = sigf(p3);
                cst = gf * cst + gi * gG;
                float h = go * tanhfast(cst);
                sx[q ^ 1][ba][DIN + half * UPC + ua] = h;    // own recurrence
                stcg(&g_h0[t][grp][half][ba][ua], h);        // publish
            }
            __threadfence();
            __syncthreads();
            if (tid == 0) st_rel(&g_f0[t][grp][half], 1);
        }
    } else {
        // ==================== L1 half-CTA ====================
        const int half = role - 2, peer = half ^ 1;
        float* sxb = &sx[0][0][0];           // rows of 256 floats
        const int gr0 = half * UPC + ua;
        const float bi = b_ih1[gr0]          + b_hh1[gr0];
        const float bf = b_ih1[HH + gr0]     + b_hh1[HH + gr0];
        const float bg = b_ih1[2*HH + gr0]   + b_hh1[2*HH + gr0];
        const float bo = b_ih1[3*HH + gr0]   + b_hh1[3*HH + gr0];
        if (tid < HH) swout[tid] = W_out[tid];
        if (tid == 0) sbout = b_out[0];
        for (int i2 = tid; i2 < BPC * HH; i2 += NTHR)
            sxb[(i2 >> 7) * 256 + HH + (i2 & 127)] = 0.0f;   // h1(-1) = 0
        float cst = 0.0f;
        const ulonglong2* wp = (const ulonglong2*)g_W1B
                             + ((size_t)(half * NB1 + seg * NB1H) * RPC + r);
        __syncthreads();

        for (int t = 0; t < TT; ++t) {
            while (ld_acq(&g_f0[t][grp][0]) == 0) { }
            while (ld_acq(&g_f0[t][grp][1]) == 0) { }
            if (t > 0) while (ld_acq(&g_f1[t - 1][grp][peer]) == 0) { }
            if (tid < 256) {   // copy full h0(t)
                int b = tid >> 5, q4 = tid & 31;
                int hh = q4 >> 4, qq = q4 & 15;
                ((float4*)&sxb[b * 256 + hh * UPC])[qq] =
                    ldcg4((const float4*)&g_h0[t][grp][hh][b][0] + qq);
            } else if (t > 0 && tid < 384) {   // copy peer h1-half(t-1)
                int idx = tid - 256;
                int b = idx >> 4, qq = idx & 15;
                ((float4*)&sxb[b * 256 + HH + peer * UPC])[qq] =
                    ldcg4((const float4*)&g_h1[t - 1][grp][peer][b][0] + qq);
            }
            __syncthreads();

            // head: out(t-1) from assembled full h1(t-1) (half-0 CTA only)
            if (half == 0 && t > 0 && tid < 64) {
                int b = tid >> 3, ch = tid & 7;
                float p = 0.0f;
                #pragma unroll
                for (int m = 0; m < 16; ++m) {
                    int u = ch * 16 + m;
                    p += sxb[b * 256 + HH + u] * swout[u];
                }
                p += __shfl_down_sync(0xffffffffu, p, 4, 8);
                p += __shfl_down_sync(0xffffffffu, p, 2, 8);
                p += __shfl_down_sync(0xffffffffu, p, 1, 8);
                if (ch == 0) out[(size_t)(t - 1) * BSZ + gb + b] = p + sbout;
            }

            float pre[BPC];
            dotseg<NB1H, 256>(wp, sxb, seg * NB1H, pre);
            #pragma unroll
            for (int b = 0; b < BPC; ++b) sg[b][seg][r] = pre[b];
            __syncthreads();

            {   // act
                float p0 = sg[ba][0][ua]           + sg[ba][1][ua]           + bi;
                float p1 = sg[ba][0][UPC + ua]     + sg[ba][1][UPC + ua]     + bf;
                float p2 = sg[ba][0][2*UPC + ua]   + sg[ba][1][2*UPC + ua]   + bg;
                float p3 = sg[ba][0][3*UPC + ua]   + sg[ba][1][3*UPC + ua]   + bo;
                float gi = sigf(p0), gf = sigf(p1);
                float gG = tanhfast(p2), go = sigf(p3);
                cst = gf * cst + gi * gG;
                float h = go * tanhfast(cst);
                sxb[ba * 256 + HH + half * UPC + ua] = h;    // own recurrence
                stcg(&g_h1[t][grp][half][ba][ua], h);        // publish
            }
            __threadfence();
            __syncthreads();
            if (tid == 0) st_rel(&g_f1[t][grp][half], 1);
        }

        // epilogue: out(TT-1) on half-0 CTA
        if (half == 0) {
            while (ld_acq(&g_f1[TT - 1][grp][1]) == 0) { }
            if (tid < 128) {
                int b = tid >> 4, qq = tid & 15;
                ((float4*)&sxb[b * 256 + HH + UPC])[qq] =
                    ldcg4((const float4*)&g_h1[TT - 1][grp][1][b][0] + qq);
            }
            __syncthreads();
            if (tid < 64) {
                int b = tid >> 3, ch = tid & 7;
                float p = 0.0f;
                #pragma unroll
                for (int m = 0; m < 16; ++m) {
                    int u = ch * 16 + m;
                    p += sxb[b * 256 + HH + u] * swout[u];
                }
                p += __shfl_down_sync(0xffffffffu, p, 4, 8);
                p += __shfl_down_sync(0xffffffffu, p, 2, 8);
                p += __shfl_down_sync(0xffffffffu, p, 1, 8);
                if (ch == 0) out[(size_t)(TT - 1) * BSZ + gb + b] = p + sbout;
            }
        }
    }
}

extern "C" void kernel_launch(void* const* d_in, const int* in_sizes, int n_in,
                              void* d_out, int out_size)
{
    const float* state = (const float*)d_in[0];
    const float* W_ih0 = (const float*)d_in[1];
    const float* W_hh0 = (const float*)d_in[2];
    const float* b_ih0 = (const float*)d_in[3];
    const float* b_hh0 = (const float*)d_in[4];
    const float* W_ih1 = (const float*)d_in[5];
    const float* W_hh1 = (const float*)d_in[6];
    const float* b_ih1 = (const float*)d_in[7];
    const float* b_hh1 = (const float*)d_in[8];
    const float* W_out = (const float*)d_in[9];
    const float* b_out = (const float*)d_in[10];
    float* out = (float*)d_out;

    prep_kernel<<<224, 512>>>(W_ih0, W_hh0, W_ih1, W_hh1);
    lstm_kernel<<<NCTA, NTHR>>>(state, b_ih0, b_hh0, b_ih1, b_hh1,
                                W_out, b_out, out);
}